// round 12
// baseline (speedup 1.0000x reference)
#include <cuda_runtime.h>
#include <math.h>

#define MARGIN 0.2f
#define EPS_V  1e-6f

// Packed accumulator: bits[0:38) sum_q (fixed-point 2^16),
//                     bits[38:52) valid count, bits[52:64) done-block count.
#define CNT_SHIFT  38
#define DONE_SHIFT 52
#define SUM_MASK   ((1ull << CNT_SHIFT) - 1ull)
#define CNT_MASK   ((1ull << (DONE_SHIFT - CNT_SHIFT)) - 1ull)
#define FIXP       65536.0

// Only global state: zero-init at load; last block resets it each run so
// every graph replay sees identical initial state.
__device__ unsigned long long g_acc;

// ---------------------------------------------------------------------------
// Warp-collective: first j with label[j] != l0 (or -1 if none -> all same).
// int4 loads: 128 labels per step; expected ~1 step for random labels.
// ---------------------------------------------------------------------------
__device__ __forceinline__ int warp_find_first_diff(const int* __restrict__ label,
                                                    int B, int lane, int l0) {
    for (int base = 0; base < B; base += 128) {
        const int j0 = base + (lane << 2);
        unsigned sub = 0u;
        if (j0 + 3 < B) {
            int4 lv = *(const int4*)(label + j0);
            sub = (lv.x != l0 ? 1u : 0u) | (lv.y != l0 ? 2u : 0u)
                | (lv.z != l0 ? 4u : 0u) | (lv.w != l0 ? 8u : 0u);
        } else {
            #pragma unroll
            for (int t = 0; t < 4; t++) {
                int j = j0 + t;
                if (j < B && label[j] != l0) sub |= 1u << t;
            }
        }
        unsigned act = __ballot_sync(0xffffffffu, sub != 0u);
        if (act) {
            int src = __ffs(act) - 1;
            unsigned ssub = __shfl_sync(0xffffffffu, sub, src);
            return base + (src << 2) + (__ffs(ssub) - 1);
        }
    }
    return -1;
}

// ---------------------------------------------------------------------------
// Warp-collective: first j with label[j]==lab_i && zidx[j]!=idx_i (or -1).
// Expected ~2 steps (label frequency ~1/256). zidx rejects are rare.
// ---------------------------------------------------------------------------
__device__ __forceinline__ int warp_find_pos(const int* __restrict__ label,
                                             const int* __restrict__ zidx,
                                             int B, int lane, int lab_i, int idx_i) {
    for (int base = 0; base < B; base += 128) {
        const int j0 = base + (lane << 2);
        unsigned sub = 0u;
        if (j0 + 3 < B) {
            int4 lv = *(const int4*)(label + j0);
            sub = (lv.x == lab_i ? 1u : 0u) | (lv.y == lab_i ? 2u : 0u)
                | (lv.z == lab_i ? 4u : 0u) | (lv.w == lab_i ? 8u : 0u);
        } else {
            #pragma unroll
            for (int t = 0; t < 4; t++) {
                int j = j0 + t;
                if (j < B && label[j] == lab_i) sub |= 1u << t;
            }
        }
        while (true) {
            unsigned act = __ballot_sync(0xffffffffu, sub != 0u);
            if (!act) break;
            int src = __ffs(act) - 1;
            unsigned ssub = __shfl_sync(0xffffffffu, sub, src);
            int j = base + (src << 2) + (__ffs(ssub) - 1);
            if (__ldg(&zidx[j]) != idx_i) return j;   // broadcast load (same j)
            if (lane == src) sub &= (sub - 1u);       // drop rejected candidate
        }
    }
    return -1;
}

// ---------------------------------------------------------------------------
// Single fused kernel: one warp per row. Only HALF the a-row is held in
// registers across the mining scans (16 regs instead of 32); the second half
// is loaded inline in the unrolled compute loop. With launch_bounds(256,6)
// this fits 6 blocks/SM (~72% occ) for much better latency hiding.
// a-loads use __ldcs (streaming) so pos/neg rows stay L1-hot.
// Tail = one packed relaxed atomicAdd per block (no fences -> no L1 flush).
// ---------------------------------------------------------------------------
__global__ void __launch_bounds__(256, 6) triplet_kernel(const float* __restrict__ z,
                                                         const int* __restrict__ label,
                                                         const int* __restrict__ zidx,
                                                         float* __restrict__ out,
                                                         int B, int C, int k,
                                                         unsigned int nblocks) {
    const int warp = threadIdx.x >> 5;
    const int lane = threadIdx.x & 31;
    const int i = blockIdx.x * 8 + warp;

    float per = 0.0f;
    float vld = 0.0f;

    if (i < B) {
        // ---- prefetch FIRST HALF of a-row (held across mining) ----
        float4 av[4];
        const bool fast = (C == 1024);
        const float4* a = (const float4*)(z + (size_t)i * C);
        if (fast) {
            #pragma unroll
            for (int u = 0; u < 4; u++)
                av[u] = __ldcs(&a[lane + (u << 5)]);
        }

        const int lab_i = __ldg(&label[i]);
        const int l0    = __ldg(&label[0]);
        const int idx_i = __ldg(&zidx[i]);

        // ---- mining (overlaps the in-flight a-row loads) ----
        int pos = -1, neg = -1;
        bool closed = false;
        if (lab_i != l0) {
            neg = 0;                                   // label[0] differs
        } else {
            neg = warp_find_first_diff(label, B, lane, l0);
            if (neg < 0) closed = true;                // all labels identical
        }

        if (!closed) {
            pos = warp_find_pos(label, zidx, B, lane, lab_i, idx_i);
        } else {
            // all-same: effective labels are -1 for j<k, l0 otherwise (k>=2)
            if (i < k) { pos = (i == 0) ? 1 : 0;       neg = k; }
            else       { pos = (i == k) ? (k + 1) : k; neg = 0; }
            if (pos >= B || neg >= B || k < 2) pos = -1;
        }

        if (pos >= 0 && neg >= 0) {
            const float4* p = (const float4*)(z + (size_t)pos * C);
            const float4* n = (const float4*)(z + (size_t)neg * C);
            float sap = 0.0f, san = 0.0f;
            if (fast) {
                #pragma unroll
                for (int u = 0; u < 8; u++) {
                    const int v = lane + (u << 5);
                    float4 avv = (u < 4) ? av[u] : __ldcs(&a[v]);  // 2nd half inline
                    float4 pv = __ldg(&p[v]);
                    float4 nv = __ldg(&n[v]);
                    float d;
                    d = avv.x - pv.x + EPS_V; sap = fmaf(d, d, sap);
                    d = avv.y - pv.y + EPS_V; sap = fmaf(d, d, sap);
                    d = avv.z - pv.z + EPS_V; sap = fmaf(d, d, sap);
                    d = avv.w - pv.w + EPS_V; sap = fmaf(d, d, sap);
                    d = avv.x - nv.x + EPS_V; san = fmaf(d, d, san);
                    d = avv.y - nv.y + EPS_V; san = fmaf(d, d, san);
                    d = avv.z - nv.z + EPS_V; san = fmaf(d, d, san);
                    d = avv.w - nv.w + EPS_V; san = fmaf(d, d, san);
                }
            } else {
                const int nvec = C >> 2;
                for (int v = lane; v < nvec; v += 32) {
                    float4 avv = __ldcs(&a[v]);
                    float4 pv = __ldg(&p[v]);
                    float4 nv = __ldg(&n[v]);
                    float d;
                    d = avv.x - pv.x + EPS_V; sap = fmaf(d, d, sap);
                    d = avv.y - pv.y + EPS_V; sap = fmaf(d, d, sap);
                    d = avv.z - pv.z + EPS_V; sap = fmaf(d, d, sap);
                    d = avv.w - pv.w + EPS_V; sap = fmaf(d, d, sap);
                    d = avv.x - nv.x + EPS_V; san = fmaf(d, d, san);
                    d = avv.y - nv.y + EPS_V; san = fmaf(d, d, san);
                    d = avv.z - nv.z + EPS_V; san = fmaf(d, d, san);
                    d = avv.w - nv.w + EPS_V; san = fmaf(d, d, san);
                }
            }
            #pragma unroll
            for (int o = 16; o > 0; o >>= 1) {
                sap += __shfl_xor_sync(0xffffffffu, sap, o);
                san += __shfl_xor_sync(0xffffffffu, san, o);
            }
            per = fmaxf(sqrtf(sap) - sqrtf(san) + MARGIN, 0.0f);
            vld = 1.0f;
        }
    }

    // ---- single-atomic deterministic tail ----
    __shared__ float s_s[8];
    __shared__ float s_c[8];
    if (lane == 0) { s_s[warp] = per; s_c[warp] = vld; }
    __syncthreads();
    if (threadIdx.x == 0) {
        double bsum = 0.0; unsigned int c = 0u;
        #pragma unroll
        for (int w = 0; w < 8; w++) { bsum += (double)s_s[w]; c += (unsigned int)s_c[w]; }
        unsigned long long q = (unsigned long long)(bsum * FIXP + 0.5);
        unsigned long long val = q
                               | ((unsigned long long)c << CNT_SHIFT)
                               | (1ull << DONE_SHIFT);
        unsigned long long old = atomicAdd(&g_acc, val);   // relaxed, no fence
        if ((old >> DONE_SHIFT) == (unsigned long long)(nblocks - 1u)) {
            unsigned long long t = old + val;
            unsigned long long sq = t & SUM_MASK;
            unsigned int cc = (unsigned int)((t >> CNT_SHIFT) & CNT_MASK);
            out[0] = (cc > 0u) ? (float)(((double)sq / FIXP) / (double)cc) : 0.0f;
            g_acc = 0ull;   // reset for next graph replay
        }
    }
}

extern "C" void kernel_launch(void* const* d_in, const int* in_sizes, int n_in,
                              void* d_out, int out_size) {
    const int* z_label = (const int*)d_in[0];
    const int* z_idx   = (const int*)d_in[1];
    const float* z     = (const float*)d_in[2];
    float* out = (float*)d_out;

    const int B = in_sizes[0];
    const int C = in_sizes[2] / B;
    int k = (int)((double)B * 0.01);
    if (k < 2) k = 2;

    const unsigned int nblocks = (unsigned int)((B + 7) / 8);
    triplet_kernel<<<nblocks, 256>>>(z, z_label, z_idx, out, B, C, k, nblocks);
}

// round 13
// speedup vs baseline: 1.0152x; 1.0152x over previous
#include <cuda_runtime.h>
#include <math.h>

#define MARGIN 0.2f
#define EPS_V  1e-6f

// Packed accumulator: bits[0:38) sum_q (fixed-point 2^16),
//                     bits[38:52) valid count, bits[52:64) done-block count.
#define CNT_SHIFT  38
#define DONE_SHIFT 52
#define SUM_MASK   ((1ull << CNT_SHIFT) - 1ull)
#define CNT_MASK   ((1ull << (DONE_SHIFT - CNT_SHIFT)) - 1ull)
#define FIXP       65536.0

// Only global state: zero-init at load; last block resets it each run.
__device__ unsigned long long g_acc;

// ---------------------------------------------------------------------------
// Warp-collective: first j with label[j] != l0 (or -1 -> all same).
// ---------------------------------------------------------------------------
__device__ __forceinline__ int warp_find_first_diff(const int* __restrict__ label,
                                                    int B, int lane, int l0) {
    for (int base = 0; base < B; base += 128) {
        const int j0 = base + (lane << 2);
        unsigned sub = 0u;
        if (j0 + 3 < B) {
            int4 lv = *(const int4*)(label + j0);
            sub = (lv.x != l0 ? 1u : 0u) | (lv.y != l0 ? 2u : 0u)
                | (lv.z != l0 ? 4u : 0u) | (lv.w != l0 ? 8u : 0u);
        } else {
            #pragma unroll
            for (int t = 0; t < 4; t++) {
                int j = j0 + t;
                if (j < B && label[j] != l0) sub |= 1u << t;
            }
        }
        unsigned act = __ballot_sync(0xffffffffu, sub != 0u);
        if (act) {
            int src = __ffs(act) - 1;
            unsigned ssub = __shfl_sync(0xffffffffu, sub, src);
            return base + (src << 2) + (__ffs(ssub) - 1);
        }
    }
    return -1;
}

// ---------------------------------------------------------------------------
// Warp-collective: first j with label[j]==lab_i && zidx[j]!=idx_i (or -1).
// ---------------------------------------------------------------------------
__device__ __forceinline__ int warp_find_pos(const int* __restrict__ label,
                                             const int* __restrict__ zidx,
                                             int B, int lane, int lab_i, int idx_i) {
    for (int base = 0; base < B; base += 128) {
        const int j0 = base + (lane << 2);
        unsigned sub = 0u;
        if (j0 + 3 < B) {
            int4 lv = *(const int4*)(label + j0);
            sub = (lv.x == lab_i ? 1u : 0u) | (lv.y == lab_i ? 2u : 0u)
                | (lv.z == lab_i ? 4u : 0u) | (lv.w == lab_i ? 8u : 0u);
        } else {
            #pragma unroll
            for (int t = 0; t < 4; t++) {
                int j = j0 + t;
                if (j < B && label[j] == lab_i) sub |= 1u << t;
            }
        }
        while (true) {
            unsigned act = __ballot_sync(0xffffffffu, sub != 0u);
            if (!act) break;
            int src = __ffs(act) - 1;
            unsigned ssub = __shfl_sync(0xffffffffu, sub, src);
            int j = base + (src << 2) + (__ffs(ssub) - 1);
            if (__ldg(&zidx[j]) != idx_i) return j;
            if (lane == src) sub &= (sub - 1u);
        }
    }
    return -1;
}

// Resolve (pos, neg) for row i. Returns false if triplet invalid.
__device__ __forceinline__ bool mine_row(const int* __restrict__ label,
                                         const int* __restrict__ zidx,
                                         int B, int k, int lane,
                                         int i, int lab_i, int l0, int idx_i,
                                         int& pos, int& neg) {
    pos = -1; neg = -1;
    bool closed = false;
    if (lab_i != l0) {
        neg = 0;
    } else {
        neg = warp_find_first_diff(label, B, lane, l0);
        if (neg < 0) closed = true;
    }
    if (!closed) {
        pos = warp_find_pos(label, zidx, B, lane, lab_i, idx_i);
    } else {
        if (i < k) { pos = (i == 0) ? 1 : 0;       neg = k; }
        else       { pos = (i == k) ? (k + 1) : k; neg = 0; }
        if (pos >= B || neg >= B || k < 2) pos = -1;
    }
    return (pos >= 0) && (neg >= 0);
}

// ---------------------------------------------------------------------------
// Fused kernel. two==1 (C==1024, B%16==0): each warp handles rows gid and
// gid+B/2 — row0 via 8 LDG.128 into registers, row1 via cp.async.cg into
// SMEM. 8KB DRAM in flight per warp; mining for both rows overlaps the
// loads; fused compute loop has 4 independent FMA chains.
// ---------------------------------------------------------------------------
__global__ void __launch_bounds__(256, 4) triplet_kernel(const float* __restrict__ z,
                                                         const int* __restrict__ label,
                                                         const int* __restrict__ zidx,
                                                         float* __restrict__ out,
                                                         int B, int C, int k,
                                                         unsigned int nblocks, int two) {
    __shared__ float s_a[8 * 1024];   // row1 staging: 8 warps x 4KB
    const int warp = threadIdx.x >> 5;
    const int lane = threadIdx.x & 31;
    const int gid = blockIdx.x * 8 + warp;

    float per_tot = 0.0f;
    float cnt_tot = 0.0f;

    if (two) {
        const int half = B >> 1;
        const int r0 = gid, r1 = gid + half;

        // ---- stream row1 into SMEM (cp.async.cg: no regs, bypasses L1) ----
        {
            const char* g1 = (const char*)(z + (size_t)r1 * 1024);
            unsigned int sb = (unsigned int)__cvta_generic_to_shared(&s_a[warp * 1024]);
            #pragma unroll
            for (int u = 0; u < 8; u++) {
                unsigned int sa = sb + (unsigned int)((lane + (u << 5)) * 16);
                asm volatile("cp.async.cg.shared.global [%0], [%1], 16;\n"
                             :: "r"(sa), "l"(g1 + (lane + (u << 5)) * 16));
            }
            asm volatile("cp.async.commit_group;\n" ::: "memory");
        }

        // ---- row0 into registers (8 back-to-back LDG.128) ----
        float4 av[8];
        const float4* a0 = (const float4*)(z + (size_t)r0 * 1024);
        #pragma unroll
        for (int u = 0; u < 8; u++)
            av[u] = a0[lane + (u << 5)];

        const int l0   = __ldg(&label[0]);
        const int lb0  = __ldg(&label[r0]);
        const int lb1  = __ldg(&label[r1]);
        const int ix0  = __ldg(&zidx[r0]);
        const int ix1  = __ldg(&zidx[r1]);

        // ---- mining both rows (overlaps in-flight loads) ----
        int pos0, neg0, pos1, neg1;
        bool v0 = mine_row(label, zidx, B, k, lane, r0, lb0, l0, ix0, pos0, neg0);
        bool v1 = mine_row(label, zidx, B, k, lane, r1, lb1, l0, ix1, pos1, neg1);

        // safe indices for invalid rows (contribution masked later)
        const int sp0 = v0 ? pos0 : 0, sn0 = v0 ? neg0 : 0;
        const int sp1 = v1 ? pos1 : 0, sn1 = v1 ? neg1 : 0;
        const float4* p0 = (const float4*)(z + (size_t)sp0 * 1024);
        const float4* n0 = (const float4*)(z + (size_t)sn0 * 1024);
        const float4* p1 = (const float4*)(z + (size_t)sp1 * 1024);
        const float4* n1 = (const float4*)(z + (size_t)sn1 * 1024);

        asm volatile("cp.async.wait_group 0;\n" ::: "memory");

        const float4* s1 = (const float4*)&s_a[warp * 1024];
        float sap0 = 0.f, san0 = 0.f, sap1 = 0.f, san1 = 0.f;
        #pragma unroll
        for (int u = 0; u < 8; u++) {
            const int v = lane + (u << 5);
            float4 A0 = av[u];
            float4 A1 = s1[v];
            float4 P0 = __ldg(&p0[v]);
            float4 N0 = __ldg(&n0[v]);
            float4 P1 = __ldg(&p1[v]);
            float4 N1 = __ldg(&n1[v]);
            float d;
            d = A0.x - P0.x + EPS_V; sap0 = fmaf(d, d, sap0);
            d = A0.y - P0.y + EPS_V; sap0 = fmaf(d, d, sap0);
            d = A0.z - P0.z + EPS_V; sap0 = fmaf(d, d, sap0);
            d = A0.w - P0.w + EPS_V; sap0 = fmaf(d, d, sap0);
            d = A0.x - N0.x + EPS_V; san0 = fmaf(d, d, san0);
            d = A0.y - N0.y + EPS_V; san0 = fmaf(d, d, san0);
            d = A0.z - N0.z + EPS_V; san0 = fmaf(d, d, san0);
            d = A0.w - N0.w + EPS_V; san0 = fmaf(d, d, san0);
            d = A1.x - P1.x + EPS_V; sap1 = fmaf(d, d, sap1);
            d = A1.y - P1.y + EPS_V; sap1 = fmaf(d, d, sap1);
            d = A1.z - P1.z + EPS_V; sap1 = fmaf(d, d, sap1);
            d = A1.w - P1.w + EPS_V; sap1 = fmaf(d, d, sap1);
            d = A1.x - N1.x + EPS_V; san1 = fmaf(d, d, san1);
            d = A1.y - N1.y + EPS_V; san1 = fmaf(d, d, san1);
            d = A1.z - N1.z + EPS_V; san1 = fmaf(d, d, san1);
            d = A1.w - N1.w + EPS_V; san1 = fmaf(d, d, san1);
        }
        #pragma unroll
        for (int o = 16; o > 0; o >>= 1) {
            sap0 += __shfl_xor_sync(0xffffffffu, sap0, o);
            san0 += __shfl_xor_sync(0xffffffffu, san0, o);
            sap1 += __shfl_xor_sync(0xffffffffu, sap1, o);
            san1 += __shfl_xor_sync(0xffffffffu, san1, o);
        }
        float per0 = v0 ? fmaxf(sqrtf(sap0) - sqrtf(san0) + MARGIN, 0.0f) : 0.0f;
        float per1 = v1 ? fmaxf(sqrtf(sap1) - sqrtf(san1) + MARGIN, 0.0f) : 0.0f;
        per_tot = per0 + per1;
        cnt_tot = (v0 ? 1.0f : 0.0f) + (v1 ? 1.0f : 0.0f);
    } else if (gid < B) {
        // ---- generic single-row path ----
        const int i = gid;
        const int lab_i = __ldg(&label[i]);
        const int l0    = __ldg(&label[0]);
        const int idx_i = __ldg(&zidx[i]);
        int pos, neg;
        bool valid = mine_row(label, zidx, B, k, lane, i, lab_i, l0, idx_i, pos, neg);
        if (valid) {
            const float4* a = (const float4*)(z + (size_t)i * C);
            const float4* p = (const float4*)(z + (size_t)pos * C);
            const float4* n = (const float4*)(z + (size_t)neg * C);
            float sap = 0.0f, san = 0.0f;
            const int nvec = C >> 2;
            for (int v = lane; v < nvec; v += 32) {
                float4 avv = a[v];
                float4 pv = __ldg(&p[v]);
                float4 nv = __ldg(&n[v]);
                float d;
                d = avv.x - pv.x + EPS_V; sap = fmaf(d, d, sap);
                d = avv.y - pv.y + EPS_V; sap = fmaf(d, d, sap);
                d = avv.z - pv.z + EPS_V; sap = fmaf(d, d, sap);
                d = avv.w - pv.w + EPS_V; sap = fmaf(d, d, sap);
                d = avv.x - nv.x + EPS_V; san = fmaf(d, d, san);
                d = avv.y - nv.y + EPS_V; san = fmaf(d, d, san);
                d = avv.z - nv.z + EPS_V; san = fmaf(d, d, san);
                d = avv.w - nv.w + EPS_V; san = fmaf(d, d, san);
            }
            #pragma unroll
            for (int o = 16; o > 0; o >>= 1) {
                sap += __shfl_xor_sync(0xffffffffu, sap, o);
                san += __shfl_xor_sync(0xffffffffu, san, o);
            }
            per_tot = fmaxf(sqrtf(sap) - sqrtf(san) + MARGIN, 0.0f);
            cnt_tot = 1.0f;
        }
    }

    // ---- single-atomic deterministic tail ----
    __shared__ float s_s[8];
    __shared__ float s_c[8];
    if (lane == 0) { s_s[warp] = per_tot; s_c[warp] = cnt_tot; }
    __syncthreads();
    if (threadIdx.x == 0) {
        double bsum = 0.0; unsigned int c = 0u;
        #pragma unroll
        for (int w = 0; w < 8; w++) { bsum += (double)s_s[w]; c += (unsigned int)s_c[w]; }
        unsigned long long q = (unsigned long long)(bsum * FIXP + 0.5);
        unsigned long long val = q
                               | ((unsigned long long)c << CNT_SHIFT)
                               | (1ull << DONE_SHIFT);
        unsigned long long old = atomicAdd(&g_acc, val);   // relaxed, no fence
        if ((old >> DONE_SHIFT) == (unsigned long long)(nblocks - 1u)) {
            unsigned long long t = old + val;
            unsigned long long sq = t & SUM_MASK;
            unsigned int cc = (unsigned int)((t >> CNT_SHIFT) & CNT_MASK);
            out[0] = (cc > 0u) ? (float)(((double)sq / FIXP) / (double)cc) : 0.0f;
            g_acc = 0ull;   // reset for next graph replay
        }
    }
}

extern "C" void kernel_launch(void* const* d_in, const int* in_sizes, int n_in,
                              void* d_out, int out_size) {
    const int* z_label = (const int*)d_in[0];
    const int* z_idx   = (const int*)d_in[1];
    const float* z     = (const float*)d_in[2];
    float* out = (float*)d_out;

    const int B = in_sizes[0];
    const int C = in_sizes[2] / B;
    int k = (int)((double)B * 0.01);
    if (k < 2) k = 2;

    int two = (C == 1024 && (B % 16) == 0) ? 1 : 0;
    unsigned int nblocks = two ? (unsigned int)(B / 16)
                               : (unsigned int)((B + 7) / 8);
    triplet_kernel<<<nblocks, 256>>>(z, z_label, z_idx, out, B, C, k, nblocks, two);
}

// round 14
// speedup vs baseline: 1.1555x; 1.1382x over previous
#include <cuda_runtime.h>
#include <math.h>

#define MARGIN 0.2f
#define EPS_V  1e-6f

// Packed accumulator: bits[0:38) sum_q (fixed-point 2^16),
//                     bits[38:52) valid count, bits[52:64) done-block count.
#define CNT_SHIFT  38
#define DONE_SHIFT 52
#define SUM_MASK   ((1ull << CNT_SHIFT) - 1ull)
#define CNT_MASK   ((1ull << (DONE_SHIFT - CNT_SHIFT)) - 1ull)
#define FIXP       65536.0

// Only global state: zero-init at load; last block resets it each run.
__device__ unsigned long long g_acc;

// ---------------------------------------------------------------------------
// Warp-collective: first j with label[j] != l0 (or -1 -> all same).
// ---------------------------------------------------------------------------
__device__ __forceinline__ int warp_find_first_diff(const int* __restrict__ label,
                                                    int B, int lane, int l0) {
    for (int base = 0; base < B; base += 128) {
        const int j0 = base + (lane << 2);
        unsigned sub = 0u;
        if (j0 + 3 < B) {
            int4 lv = *(const int4*)(label + j0);
            sub = (lv.x != l0 ? 1u : 0u) | (lv.y != l0 ? 2u : 0u)
                | (lv.z != l0 ? 4u : 0u) | (lv.w != l0 ? 8u : 0u);
        } else {
            #pragma unroll
            for (int t = 0; t < 4; t++) {
                int j = j0 + t;
                if (j < B && label[j] != l0) sub |= 1u << t;
            }
        }
        unsigned act = __ballot_sync(0xffffffffu, sub != 0u);
        if (act) {
            int src = __ffs(act) - 1;
            unsigned ssub = __shfl_sync(0xffffffffu, sub, src);
            return base + (src << 2) + (__ffs(ssub) - 1);
        }
    }
    return -1;
}

// ---------------------------------------------------------------------------
// Warp-collective: first j with label[j]==lab_i && zidx[j]!=idx_i (or -1).
// ---------------------------------------------------------------------------
__device__ __forceinline__ int warp_find_pos(const int* __restrict__ label,
                                             const int* __restrict__ zidx,
                                             int B, int lane, int lab_i, int idx_i) {
    for (int base = 0; base < B; base += 128) {
        const int j0 = base + (lane << 2);
        unsigned sub = 0u;
        if (j0 + 3 < B) {
            int4 lv = *(const int4*)(label + j0);
            sub = (lv.x == lab_i ? 1u : 0u) | (lv.y == lab_i ? 2u : 0u)
                | (lv.z == lab_i ? 4u : 0u) | (lv.w == lab_i ? 8u : 0u);
        } else {
            #pragma unroll
            for (int t = 0; t < 4; t++) {
                int j = j0 + t;
                if (j < B && label[j] == lab_i) sub |= 1u << t;
            }
        }
        while (true) {
            unsigned act = __ballot_sync(0xffffffffu, sub != 0u);
            if (!act) break;
            int src = __ffs(act) - 1;
            unsigned ssub = __shfl_sync(0xffffffffu, sub, src);
            int j = base + (src << 2) + (__ffs(ssub) - 1);
            if (__ldg(&zidx[j]) != idx_i) return j;   // broadcast load (same j)
            if (lane == src) sub &= (sub - 1u);       // drop rejected candidate
        }
    }
    return -1;
}

// ---------------------------------------------------------------------------
// Single fused kernel (R11 body + row-0 staged in SMEM for the neg stream).
// One warp per row; 8 back-to-back LDG.128 prefetch the a-row; row 0 (the neg
// row for ~255/256 of samples) is staged cooperatively into SMEM and served
// via LDS in the hot loop -> the compute loop carries only the pos LDG
// stream. Tail = one packed relaxed atomicAdd per block (no fences).
// ---------------------------------------------------------------------------
__global__ void __launch_bounds__(256) triplet_kernel(const float* __restrict__ z,
                                                      const int* __restrict__ label,
                                                      const int* __restrict__ zidx,
                                                      float* __restrict__ out,
                                                      int B, int C, int k,
                                                      unsigned int nblocks) {
    __shared__ float s_z0[1024];   // row 0 staging (4 KB)
    const int warp = threadIdx.x >> 5;
    const int lane = threadIdx.x & 31;
    const int tid  = threadIdx.x;
    const int i = blockIdx.x * 8 + warp;

    const bool fast = (C == 1024);

    // ---- stage row 0 into SMEM (1 float4 per thread, overlaps a-prefetch) --
    float4 z0t;
    if (fast) z0t = __ldg(&((const float4*)z)[tid]);   // row 0, element tid

    float per = 0.0f;
    float vld = 0.0f;

    // ---- prefetch a-row (the only DRAM-streaming operand) ----
    float4 av[8];
    if (fast && i < B) {
        const float4* a = (const float4*)(z + (size_t)i * 1024);
        #pragma unroll
        for (int u = 0; u < 8; u++)
            av[u] = a[lane + (u << 5)];
    }

    if (fast) {
        ((float4*)s_z0)[tid] = z0t;   // waits only on the row-0 load
        __syncthreads();
    }

    if (i < B) {
        const int lab_i = __ldg(&label[i]);
        const int l0    = __ldg(&label[0]);
        const int idx_i = __ldg(&zidx[i]);

        // ---- mining (overlaps the in-flight a-row loads) ----
        int pos = -1, neg = -1;
        bool closed = false;
        if (lab_i != l0) {
            neg = 0;                                   // label[0] differs
        } else {
            neg = warp_find_first_diff(label, B, lane, l0);
            if (neg < 0) closed = true;                // all labels identical
        }

        if (!closed) {
            pos = warp_find_pos(label, zidx, B, lane, lab_i, idx_i);
        } else {
            // all-same: effective labels are -1 for j<k, l0 otherwise (k>=2)
            if (i < k) { pos = (i == 0) ? 1 : 0;       neg = k; }
            else       { pos = (i == k) ? (k + 1) : k; neg = 0; }
            if (pos >= B || neg >= B || k < 2) pos = -1;
        }

        if (pos >= 0 && neg >= 0) {
            const float4* p = (const float4*)(z + (size_t)pos * C);
            float sap = 0.0f, san = 0.0f;
            if (fast) {
                if (neg == 0) {
                    // hot path: neg row from SMEM (LDS), pos via LDG
                    const float4* ns = (const float4*)s_z0;
                    #pragma unroll
                    for (int u = 0; u < 8; u++) {
                        const int v = lane + (u << 5);
                        float4 pv = __ldg(&p[v]);
                        float4 nv = ns[v];
                        float d;
                        d = av[u].x - pv.x + EPS_V; sap = fmaf(d, d, sap);
                        d = av[u].y - pv.y + EPS_V; sap = fmaf(d, d, sap);
                        d = av[u].z - pv.z + EPS_V; sap = fmaf(d, d, sap);
                        d = av[u].w - pv.w + EPS_V; sap = fmaf(d, d, sap);
                        d = av[u].x - nv.x + EPS_V; san = fmaf(d, d, san);
                        d = av[u].y - nv.y + EPS_V; san = fmaf(d, d, san);
                        d = av[u].z - nv.z + EPS_V; san = fmaf(d, d, san);
                        d = av[u].w - nv.w + EPS_V; san = fmaf(d, d, san);
                    }
                } else {
                    const float4* n = (const float4*)(z + (size_t)neg * C);
                    #pragma unroll
                    for (int u = 0; u < 8; u++) {
                        const int v = lane + (u << 5);
                        float4 pv = __ldg(&p[v]);
                        float4 nv = __ldg(&n[v]);
                        float d;
                        d = av[u].x - pv.x + EPS_V; sap = fmaf(d, d, sap);
                        d = av[u].y - pv.y + EPS_V; sap = fmaf(d, d, sap);
                        d = av[u].z - pv.z + EPS_V; sap = fmaf(d, d, sap);
                        d = av[u].w - pv.w + EPS_V; sap = fmaf(d, d, sap);
                        d = av[u].x - nv.x + EPS_V; san = fmaf(d, d, san);
                        d = av[u].y - nv.y + EPS_V; san = fmaf(d, d, san);
                        d = av[u].z - nv.z + EPS_V; san = fmaf(d, d, san);
                        d = av[u].w - nv.w + EPS_V; san = fmaf(d, d, san);
                    }
                }
            } else {
                const float4* a = (const float4*)(z + (size_t)i * C);
                const float4* n = (const float4*)(z + (size_t)neg * C);
                const int nvec = C >> 2;
                for (int v = lane; v < nvec; v += 32) {
                    float4 avv = a[v];
                    float4 pv = __ldg(&p[v]);
                    float4 nv = __ldg(&n[v]);
                    float d;
                    d = avv.x - pv.x + EPS_V; sap = fmaf(d, d, sap);
                    d = avv.y - pv.y + EPS_V; sap = fmaf(d, d, sap);
                    d = avv.z - pv.z + EPS_V; sap = fmaf(d, d, sap);
                    d = avv.w - pv.w + EPS_V; sap = fmaf(d, d, sap);
                    d = avv.x - nv.x + EPS_V; san = fmaf(d, d, san);
                    d = avv.y - nv.y + EPS_V; san = fmaf(d, d, san);
                    d = avv.z - nv.z + EPS_V; san = fmaf(d, d, san);
                    d = avv.w - nv.w + EPS_V; san = fmaf(d, d, san);
                }
            }
            #pragma unroll
            for (int o = 16; o > 0; o >>= 1) {
                sap += __shfl_xor_sync(0xffffffffu, sap, o);
                san += __shfl_xor_sync(0xffffffffu, san, o);
            }
            per = fmaxf(sqrtf(sap) - sqrtf(san) + MARGIN, 0.0f);
            vld = 1.0f;
        }
    }

    // ---- single-atomic deterministic tail ----
    __shared__ float s_s[8];
    __shared__ float s_c[8];
    if (lane == 0) { s_s[warp] = per; s_c[warp] = vld; }
    __syncthreads();
    if (threadIdx.x == 0) {
        double bsum = 0.0; unsigned int c = 0u;
        #pragma unroll
        for (int w = 0; w < 8; w++) { bsum += (double)s_s[w]; c += (unsigned int)s_c[w]; }
        unsigned long long q = (unsigned long long)(bsum * FIXP + 0.5);
        unsigned long long val = q
                               | ((unsigned long long)c << CNT_SHIFT)
                               | (1ull << DONE_SHIFT);
        unsigned long long old = atomicAdd(&g_acc, val);   // relaxed, no fence
        if ((old >> DONE_SHIFT) == (unsigned long long)(nblocks - 1u)) {
            unsigned long long t = old + val;
            unsigned long long sq = t & SUM_MASK;
            unsigned int cc = (unsigned int)((t >> CNT_SHIFT) & CNT_MASK);
            out[0] = (cc > 0u) ? (float)(((double)sq / FIXP) / (double)cc) : 0.0f;
            g_acc = 0ull;   // reset for next graph replay
        }
    }
}

extern "C" void kernel_launch(void* const* d_in, const int* in_sizes, int n_in,
                              void* d_out, int out_size) {
    const int* z_label = (const int*)d_in[0];
    const int* z_idx   = (const int*)d_in[1];
    const float* z     = (const float*)d_in[2];
    float* out = (float*)d_out;

    const int B = in_sizes[0];
    const int C = in_sizes[2] / B;
    int k = (int)((double)B * 0.01);
    if (k < 2) k = 2;

    const unsigned int nblocks = (unsigned int)((B + 7) / 8);
    triplet_kernel<<<nblocks, 256>>>(z, z_label, z_idx, out, B, C, k, nblocks);
}